// round 9
// baseline (speedup 1.0000x reference)
#include <cuda_runtime.h>
#include <cstdint>

#define SCALE 0.17677669529663687f     // 32^-0.5
typedef unsigned long long ull;

// Packed dual-fp32 FMA (sm_100+): acc(2xf32) += a(2xf32) * b(2xf32)
#define FMA2(acc, a, b) \
    asm("fma.rn.f32x2 %0, %1, %2, %0;" : "+l"(acc) : "l"(a), "l"(b))

#define CP_ASYNC16(dst_u32, src_ptr) \
    asm volatile("cp.async.ca.shared.global [%0], [%1], 16;" \
                 :: "r"(dst_u32), "l"(src_ptr))
#define CP_COMMIT() asm volatile("cp.async.commit_group;")
#define CP_WAIT0()  asm volatile("cp.async.wait_group 0;" ::: "memory")

// smem layout (float offsets)
#define OFF_KT 0          // Kt[32][512]   d-major K
#define OFF_VT 16384      // Vt[32][512]   c-major V, k-pair swizzled by ch-grp
#define OFF_PD 32768      // Pd[32][516] ALIASED by Red[16][32][36] (18432 f)
#define OFF_QD 51200      // Qd[32][68]  duplicated (q,q) pairs
#define OFF_QR 53376      // Qr[32][36]  raw Q staging (cp.async)
#define OFF_SR 54528      // Sr[2][32]   softmax partial sums
#define OFF_W  54592      // conv w [32*9]
#define OFF_B  54880      // conv b [32]
#define SMEM_FLOATS 54912 // 219648 bytes

// ---------------------------------------------------------------------------
// R6 structure (307us) + ONE change: S-phase q operand comes from a
// pre-duplicated (q,q) pair buffer Qd -> kills 8 PACK2 + swaps 4 LDS.64 for
// 4 LDS.128 broadcasts per warp per d-pair (issue slots 48 -> 40).
// One CTA per (window, head). 512 threads, 16 warps, 16 passes of 32 q-rows.
// ---------------------------------------------------------------------------
__global__ __launch_bounds__(512, 1)
void fused_attn_kernel(const float* __restrict__ qkv,
                       const float* __restrict__ cw,
                       const float* __restrict__ cb,
                       float* __restrict__ attn_out,
                       float* __restrict__ xout) {
    extern __shared__ float sm[];
    float* Kt  = sm + OFF_KT;
    float* Vt  = sm + OFF_VT;
    float* Pd  = sm + OFF_PD;
    float* Red = sm + OFF_PD;      // alias (Pd dead when Red live)
    float* Qd  = sm + OFF_QD;
    float* Qr  = sm + OFF_QR;
    float* Sr  = sm + OFF_SR;
    float* Wsh = sm + OFF_W;
    float* Bsh = sm + OFF_B;

    int wh = blockIdx.x;  int n = wh >> 3, h = wh & 7;
    int b  = n >> 3,      w2 = n & 7;
    int tid = threadIdx.x, lane = tid & 31, warp = tid >> 5;
    int wg = warp & 7, half = warp >> 3;
    int colb = half * 256;                     // S-phase column half

    const float* Qg = qkv + (size_t)(0 + b) * 4096 * 256;
    const float* Kg = qkv + (size_t)(4 + b) * 4096 * 256;
    const float* Vg = qkv + (size_t)(8 + b) * 4096 * 256;

    uint32_t qr_base = (uint32_t)__cvta_generic_to_shared(Qr);
    int qrow = (tid & 255) >> 3, qcq = tid & 7;

    // ---- prologue: prefetch Q(pass 0); fill Kt, Vt, conv params ----
    if (tid < 256) {
        int l = (qrow >> 3) * 64 + w2 * 8 + (qrow & 7);
        CP_ASYNC16(qr_base + (uint32_t)(qrow * 36 + qcq * 4) * 4,
                   Qg + (size_t)l * 256 + h * 32 + qcq * 4);
    }
    CP_COMMIT();
    {   // Kt: one column per thread
        int c = tid;
        int l = (c >> 3) * 64 + w2 * 8 + (c & 7);
        const float4* src = (const float4*)(Kg + (size_t)l * 256 + h * 32);
        #pragma unroll
        for (int v4 = 0; v4 < 8; v4++) {
            float4 v = src[v4];
            Kt[(4 * v4 + 0) * 512 + c] = v.x;
            Kt[(4 * v4 + 1) * 512 + c] = v.y;
            Kt[(4 * v4 + 2) * 512 + c] = v.z;
            Kt[(4 * v4 + 3) * 512 + c] = v.w;
        }
    }
    {   // Vt transposed + k-pair swizzle (slot = (k>>1) ^ 4*((c>>3)&3))
        int c  = tid & 31;
        int sw = 4 * ((c >> 3) & 3);
        for (int k = tid >> 5; k < 512; k += 16) {
            int l = (k >> 3) * 64 + w2 * 8 + (k & 7);
            Vt[c * 512 + 2 * ((k >> 1) ^ sw) + (k & 1)] =
                Vg[(size_t)l * 256 + h * 32 + c];
        }
    }
    for (int i = tid; i < 288; i += 512) Wsh[i] = cw[(h * 32) * 9 + i];
    if (tid < 32) Bsh[tid] = cb[h * 32 + tid];
    CP_WAIT0();
    if (tid < 256) {   // dup own copied floats into Qd pairs
        float4 qv = *(const float4*)(Qr + qrow * 36 + qcq * 4);
        *(float4*)(Qd + qrow * 68 + 8 * qcq)     = make_float4(qv.x, qv.x, qv.y, qv.y);
        *(float4*)(Qd + qrow * 68 + 8 * qcq + 4) = make_float4(qv.z, qv.z, qv.w, qv.w);
    }
    __syncthreads();

    float* outp = attn_out + (size_t)wh * 512 * 512;
    const float* Ktb = Kt + colb + 4 * lane;

    // PV mapping: lane = (rs, cq): rows {rs + 8j}, channels {8cq .. 8cq+7}
    int rs = lane >> 2, cq = lane & 3;
    int vsw = cq << 2;

    for (int pass = 0; pass < 16; pass++) {
        // ============ S phase: warp = 4 rows x 256 cols (R6 tile) =========
        ull sacc[4][4];
        #pragma unroll
        for (int r = 0; r < 4; r++)
            #pragma unroll
            for (int j = 0; j < 4; j++) sacc[r][j] = 0ull;

        const float* Qb = Qd + (wg * 4) * 68;
        #pragma unroll 4
        for (int d = 0; d < 32; d += 2) {
            ulonglong2 qq0 = *(const ulonglong2*)(Qb + 0 * 68 + 2 * d);
            ulonglong2 qq1 = *(const ulonglong2*)(Qb + 1 * 68 + 2 * d);
            ulonglong2 qq2 = *(const ulonglong2*)(Qb + 2 * 68 + 2 * d);
            ulonglong2 qq3 = *(const ulonglong2*)(Qb + 3 * 68 + 2 * d);
            #pragma unroll
            for (int p = 0; p < 2; p++) {
                ulonglong2 kv0 = *(const ulonglong2*)(Ktb + d * 512 + 128 * p);
                ulonglong2 kv1 = *(const ulonglong2*)(Ktb + (d + 1) * 512 + 128 * p);
                FMA2(sacc[0][2 * p],     kv0.x, qq0.x);
                FMA2(sacc[0][2 * p + 1], kv0.y, qq0.x);
                FMA2(sacc[1][2 * p],     kv0.x, qq1.x);
                FMA2(sacc[1][2 * p + 1], kv0.y, qq1.x);
                FMA2(sacc[2][2 * p],     kv0.x, qq2.x);
                FMA2(sacc[2][2 * p + 1], kv0.y, qq2.x);
                FMA2(sacc[3][2 * p],     kv0.x, qq3.x);
                FMA2(sacc[3][2 * p + 1], kv0.y, qq3.x);
                FMA2(sacc[0][2 * p],     kv1.x, qq0.y);
                FMA2(sacc[0][2 * p + 1], kv1.y, qq0.y);
                FMA2(sacc[1][2 * p],     kv1.x, qq1.y);
                FMA2(sacc[1][2 * p + 1], kv1.y, qq1.y);
                FMA2(sacc[2][2 * p],     kv1.x, qq2.y);
                FMA2(sacc[2][2 * p + 1], kv1.y, qq2.y);
                FMA2(sacc[3][2 * p],     kv1.x, qq3.y);
                FMA2(sacc[3][2 * p + 1], kv1.y, qq3.y);
            }
        }

        // ========== softmax (no max-subtract) + attn STG + P STS ==========
        float v[4][8];
        #pragma unroll
        for (int rr = 0; rr < 4; rr++) {
            float s = 0.f;
            #pragma unroll
            for (int u = 0; u < 4; u++) {
                float2 f = *(float2*)&sacc[rr][u];
                float e0 = __expf(f.x * SCALE);
                float e1 = __expf(f.y * SCALE);
                v[rr][2 * u] = e0; v[rr][2 * u + 1] = e1;
                s += e0 + e1;
            }
            #pragma unroll
            for (int off = 16; off; off >>= 1)
                s += __shfl_xor_sync(0xffffffffu, s, off);
            if (lane == 0) Sr[half * 32 + wg * 4 + rr] = s;
        }
        __syncthreads();                       // (1) Sr ready
        #pragma unroll
        for (int rr = 0; rr < 4; rr++) {
            int row = wg * 4 + rr;
            float inv = 1.0f / (Sr[row] + Sr[32 + row]);
            float* orow = outp + (size_t)(pass * 32 + row) * 512 + colb + 4 * lane;
            float* prow = Pd + row * 516 + colb + 4 * lane;
            #pragma unroll
            for (int p = 0; p < 2; p++) {
                float4 o = make_float4(v[rr][4 * p] * inv, v[rr][4 * p + 1] * inv,
                                       v[rr][4 * p + 2] * inv, v[rr][4 * p + 3] * inv);
                *(float4*)(orow + 128 * p) = o;
                *(float4*)(prow + 128 * p) = o;
            }
        }
        __syncthreads();                       // (2) Pd ready

        // prefetch Q for next pass (overlaps PV)
        if (pass < 15 && tid < 256) {
            int grow = (pass + 1) * 32 + qrow;
            int l = (grow >> 3) * 64 + w2 * 8 + (grow & 7);
            CP_ASYNC16(qr_base + (uint32_t)(qrow * 36 + qcq * 4) * 4,
                       Qg + (size_t)l * 256 + h * 32 + qcq * 4);
        }
        CP_COMMIT();

        // ================= PV phase (warp k-range: 16 k-pairs) ============
        ull pacc[4][8];
        #pragma unroll
        for (int j = 0; j < 4; j++)
            #pragma unroll
            for (int i = 0; i < 8; i++) pacc[j][i] = 0ull;
        {
            const float* Pk = Pd + rs * 516 + 32 * warp;
            const float* Vk = Vt + (8 * cq) * 512 + 32 * warp;
            #pragma unroll 4
            for (int a = 0; a < 16; a++) {
                ull p0 = *(const ull*)(Pk + 0 * 4128 + 2 * a);   // 8*516
                ull p1 = *(const ull*)(Pk + 1 * 4128 + 2 * a);
                ull p2 = *(const ull*)(Pk + 2 * 4128 + 2 * a);
                ull p3 = *(const ull*)(Pk + 3 * 4128 + 2 * a);
                int voff = 2 * (a ^ vsw);
                #pragma unroll
                for (int i = 0; i < 8; i++) {
                    ull vv = *(const ull*)(Vk + i * 512 + voff);
                    FMA2(pacc[0][i], p0, vv);
                    FMA2(pacc[1][i], p1, vv);
                    FMA2(pacc[2][i], p2, vv);
                    FMA2(pacc[3][i], p3, vv);
                }
            }
        }
        __syncthreads();                       // (3) PV done, Pd dead

        // ---- per-warp partials into Red[16][32][36] (aliases Pd) ----
        {
            float* rw = Red + warp * 32 * 36;
            #pragma unroll
            for (int j = 0; j < 4; j++) {
                int row = rs + 8 * j;
                float4 a4, b4;
                float2 f;
                f = *(float2*)&pacc[j][0]; a4.x = f.x + f.y;
                f = *(float2*)&pacc[j][1]; a4.y = f.x + f.y;
                f = *(float2*)&pacc[j][2]; a4.z = f.x + f.y;
                f = *(float2*)&pacc[j][3]; a4.w = f.x + f.y;
                f = *(float2*)&pacc[j][4]; b4.x = f.x + f.y;
                f = *(float2*)&pacc[j][5]; b4.y = f.x + f.y;
                f = *(float2*)&pacc[j][6]; b4.z = f.x + f.y;
                f = *(float2*)&pacc[j][7]; b4.w = f.x + f.y;
                *(float4*)(rw + row * 36 + 8 * cq)     = a4;
                *(float4*)(rw + row * 36 + 8 * cq + 4) = b4;
            }
        }
        __syncthreads();                       // (4) Red ready

        // ---- reduce 16 partials + fused LePE + STG x (threads 0..255) ----
        if (tid < 256) {
            int r  = tid >> 3;                 // 0..31 local row
            int c0 = (tid & 7) * 4;            // channel quad
            float4 o = make_float4(0.f, 0.f, 0.f, 0.f);
            #pragma unroll
            for (int w = 0; w < 16; w++) {
                float4 t4 = *(const float4*)(Red + (w * 32 + r) * 36 + c0);
                o.x += t4.x; o.y += t4.y; o.z += t4.z; o.w += t4.w;
            }
            int t  = pass * 32 + r;            // window token
            int hs = t >> 3, ws = t & 7;
            float ov[4] = {o.x + Bsh[c0], o.y + Bsh[c0 + 1],
                           o.z + Bsh[c0 + 2], o.w + Bsh[c0 + 3]};
            int swc = 4 * ((c0 >> 3) & 3);
            #pragma unroll
            for (int dy = -1; dy <= 1; dy++) {
                if ((unsigned)(hs + dy) >= 64u) continue;
                #pragma unroll
                for (int dx = -1; dx <= 1; dx++) {
                    if ((unsigned)(ws + dx) >= 8u) continue;
                    int kk = t + dy * 8 + dx;
                    int ko = 2 * ((kk >> 1) ^ swc) + (kk & 1);
                    int wi = (dy + 1) * 3 + (dx + 1);
                    #pragma unroll
                    for (int cc = 0; cc < 4; cc++)
                        ov[cc] += Vt[(c0 + cc) * 512 + ko] * Wsh[(c0 + cc) * 9 + wi];
                }
            }
            int l = hs * 64 + w2 * 8 + ws;
            *(float4*)(xout + ((size_t)b * 4096 + l) * 256 + h * 32 + c0) =
                make_float4(ov[0], ov[1], ov[2], ov[3]);
        }

        CP_WAIT0();                            // Qr(pass+1) landed
        if (pass < 15 && tid < 256) {          // dup own bytes into Qd pairs
            float4 qv = *(const float4*)(Qr + qrow * 36 + qcq * 4);
            *(float4*)(Qd + qrow * 68 + 8 * qcq)     = make_float4(qv.x, qv.x, qv.y, qv.y);
            *(float4*)(Qd + qrow * 68 + 8 * qcq + 4) = make_float4(qv.z, qv.z, qv.w, qv.w);
        }
        __syncthreads();                       // (5) epilogue done; Qd publish
    }
}

// ---------------------------------------------------------------------------
extern "C" void kernel_launch(void* const* d_in, const int* in_sizes, int n_in,
                              void* d_out, int out_size) {
    const float* qkv = (const float*)d_in[0];
    const float* cw  = (const float*)d_in[1];
    const float* cb  = (const float*)d_in[2];
    float* xout = (float*)d_out;
    float* attn = xout + (size_t)4 * 4096 * 256;    // x first, then attn

    const int SMEM = SMEM_FLOATS * 4;               // 219648 B
    cudaFuncSetAttribute(fused_attn_kernel,
                         cudaFuncAttributeMaxDynamicSharedMemorySize, SMEM);

    fused_attn_kernel<<<256, 512, SMEM>>>(qkv, cw, cb, attn, xout);
}

// round 10
// speedup vs baseline: 1.0613x; 1.0613x over previous
#include <cuda_runtime.h>
#include <cstdint>

#define SCALE 0.17677669529663687f     // 32^-0.5
typedef unsigned long long ull;

// Packed dual-fp32 FMA (sm_100+): acc(2xf32) += a(2xf32) * b(2xf32)
#define FMA2(acc, a, b) \
    asm("fma.rn.f32x2 %0, %1, %2, %0;" : "+l"(acc) : "l"(a), "l"(b))
// Duplicate a scalar float into both lanes of a 64-bit pack
#define PACK2(u, f) \
    asm("mov.b64 %0, {%1, %2};" : "=l"(u) : "f"(f), "f"(f))

#define CP_ASYNC16(dst_u32, src_ptr) \
    asm volatile("cp.async.ca.shared.global [%0], [%1], 16;" \
                 :: "r"(dst_u32), "l"(src_ptr))
#define CP_COMMIT() asm volatile("cp.async.commit_group;")
#define CP_WAIT0()  asm volatile("cp.async.wait_group 0;" ::: "memory")

// smem layout (float offsets)
#define OFF_KT 0          // Kt[32][512]   d-major K
#define OFF_VT 16384      // Vt[32][512]   c-major V, k-pair swizzled by ch-grp
#define OFF_PD 32768      // Pd[32][516] ALIASED by Red[16][32][36] (18432 f)
#define OFF_QR 51200      // Qr[32][36]  raw Q staging (cp.async)
#define OFF_SR 52352      // Sr[2][32]   softmax partial sums
#define OFF_W  52416      // conv w [32*9]
#define OFF_B  52704      // conv b [32]
#define SMEM_FLOATS 52736 // 210944 bytes

// ---------------------------------------------------------------------------
// 307us champion (R6) + ONE change: epilogue LePE conv remapped to
// (warp = channel quad, lane = token row) -> V tap loads go from 8-way bank
// conflict to ~conflict-free (fixed c per warp; ko spreads banks over rows).
// One CTA per (window, head). 512 threads, 16 warps, 16 passes of 32 q-rows.
// ---------------------------------------------------------------------------
__global__ __launch_bounds__(512, 1)
void fused_attn_kernel(const float* __restrict__ qkv,
                       const float* __restrict__ cw,
                       const float* __restrict__ cb,
                       float* __restrict__ attn_out,
                       float* __restrict__ xout) {
    extern __shared__ float sm[];
    float* Kt  = sm + OFF_KT;
    float* Vt  = sm + OFF_VT;
    float* Pd  = sm + OFF_PD;
    float* Red = sm + OFF_PD;      // alias (Pd dead when Red live)
    float* Qr  = sm + OFF_QR;
    float* Sr  = sm + OFF_SR;
    float* Wsh = sm + OFF_W;
    float* Bsh = sm + OFF_B;

    int wh = blockIdx.x;  int n = wh >> 3, h = wh & 7;
    int b  = n >> 3,      w2 = n & 7;
    int tid = threadIdx.x, lane = tid & 31, warp = tid >> 5;
    int wg = warp & 7, half = warp >> 3;
    int colb = half * 256;                     // S-phase column half

    const float* Qg = qkv + (size_t)(0 + b) * 4096 * 256;
    const float* Kg = qkv + (size_t)(4 + b) * 4096 * 256;
    const float* Vg = qkv + (size_t)(8 + b) * 4096 * 256;

    uint32_t qr_base = (uint32_t)__cvta_generic_to_shared(Qr);
    int qrow = (tid & 255) >> 3, qcq = tid & 7;

    // ---- prologue: prefetch Q(pass 0); fill Kt, Vt, conv params ----
    if (tid < 256) {
        int l = (qrow >> 3) * 64 + w2 * 8 + (qrow & 7);
        CP_ASYNC16(qr_base + (uint32_t)(qrow * 36 + qcq * 4) * 4,
                   Qg + (size_t)l * 256 + h * 32 + qcq * 4);
    }
    CP_COMMIT();
    {   // Kt: one column per thread
        int c = tid;
        int l = (c >> 3) * 64 + w2 * 8 + (c & 7);
        const float4* src = (const float4*)(Kg + (size_t)l * 256 + h * 32);
        #pragma unroll
        for (int v4 = 0; v4 < 8; v4++) {
            float4 v = src[v4];
            Kt[(4 * v4 + 0) * 512 + c] = v.x;
            Kt[(4 * v4 + 1) * 512 + c] = v.y;
            Kt[(4 * v4 + 2) * 512 + c] = v.z;
            Kt[(4 * v4 + 3) * 512 + c] = v.w;
        }
    }
    {   // Vt transposed + k-pair swizzle (slot = (k>>1) ^ 4*((c>>3)&3))
        int c  = tid & 31;
        int sw = 4 * ((c >> 3) & 3);
        for (int k = tid >> 5; k < 512; k += 16) {
            int l = (k >> 3) * 64 + w2 * 8 + (k & 7);
            Vt[c * 512 + 2 * ((k >> 1) ^ sw) + (k & 1)] =
                Vg[(size_t)l * 256 + h * 32 + c];
        }
    }
    for (int i = tid; i < 288; i += 512) Wsh[i] = cw[(h * 32) * 9 + i];
    if (tid < 32) Bsh[tid] = cb[h * 32 + tid];
    CP_WAIT0();
    __syncthreads();

    float* outp = attn_out + (size_t)wh * 512 * 512;
    const float* Ktb = Kt + colb + 4 * lane;

    // PV mapping: lane = (rs, cq): rows {rs + 8j}, channels {8cq .. 8cq+7}
    int rs = lane >> 2, cq = lane & 3;
    int vsw = cq << 2;

    for (int pass = 0; pass < 16; pass++) {
        // ============ S phase: warp = 4 rows x 256 cols ============
        ull sacc[4][4];
        #pragma unroll
        for (int r = 0; r < 4; r++)
            #pragma unroll
            for (int j = 0; j < 4; j++) sacc[r][j] = 0ull;

        const float* Qb = Qr + (wg * 4) * 36;
        #pragma unroll 4
        for (int d = 0; d < 32; d += 2) {
            float2 qf0 = *(const float2*)(Qb + 0 * 36 + d);
            float2 qf1 = *(const float2*)(Qb + 1 * 36 + d);
            float2 qf2 = *(const float2*)(Qb + 2 * 36 + d);
            float2 qf3 = *(const float2*)(Qb + 3 * 36 + d);
            ull q0x, q0y, q1x, q1y, q2x, q2y, q3x, q3y;
            PACK2(q0x, qf0.x); PACK2(q0y, qf0.y);
            PACK2(q1x, qf1.x); PACK2(q1y, qf1.y);
            PACK2(q2x, qf2.x); PACK2(q2y, qf2.y);
            PACK2(q3x, qf3.x); PACK2(q3y, qf3.y);
            #pragma unroll
            for (int p = 0; p < 2; p++) {
                ulonglong2 kv0 = *(const ulonglong2*)(Ktb + d * 512 + 128 * p);
                ulonglong2 kv1 = *(const ulonglong2*)(Ktb + (d + 1) * 512 + 128 * p);
                FMA2(sacc[0][2 * p],     kv0.x, q0x);
                FMA2(sacc[0][2 * p + 1], kv0.y, q0x);
                FMA2(sacc[1][2 * p],     kv0.x, q1x);
                FMA2(sacc[1][2 * p + 1], kv0.y, q1x);
                FMA2(sacc[2][2 * p],     kv0.x, q2x);
                FMA2(sacc[2][2 * p + 1], kv0.y, q2x);
                FMA2(sacc[3][2 * p],     kv0.x, q3x);
                FMA2(sacc[3][2 * p + 1], kv0.y, q3x);
                FMA2(sacc[0][2 * p],     kv1.x, q0y);
                FMA2(sacc[0][2 * p + 1], kv1.y, q0y);
                FMA2(sacc[1][2 * p],     kv1.x, q1y);
                FMA2(sacc[1][2 * p + 1], kv1.y, q1y);
                FMA2(sacc[2][2 * p],     kv1.x, q2y);
                FMA2(sacc[2][2 * p + 1], kv1.y, q2y);
                FMA2(sacc[3][2 * p],     kv1.x, q3y);
                FMA2(sacc[3][2 * p + 1], kv1.y, q3y);
            }
        }

        // ========== softmax (no max-subtract) + attn STG + P STS ==========
        float v[4][8];
        #pragma unroll
        for (int rr = 0; rr < 4; rr++) {
            float s = 0.f;
            #pragma unroll
            for (int u = 0; u < 4; u++) {
                float2 f = *(float2*)&sacc[rr][u];
                float e0 = __expf(f.x * SCALE);
                float e1 = __expf(f.y * SCALE);
                v[rr][2 * u] = e0; v[rr][2 * u + 1] = e1;
                s += e0 + e1;
            }
            #pragma unroll
            for (int off = 16; off; off >>= 1)
                s += __shfl_xor_sync(0xffffffffu, s, off);
            if (lane == 0) Sr[half * 32 + wg * 4 + rr] = s;
        }
        __syncthreads();                       // (1) Sr ready
        #pragma unroll
        for (int rr = 0; rr < 4; rr++) {
            int row = wg * 4 + rr;
            float inv = 1.0f / (Sr[row] + Sr[32 + row]);
            float* orow = outp + (size_t)(pass * 32 + row) * 512 + colb + 4 * lane;
            float* prow = Pd + row * 516 + colb + 4 * lane;
            #pragma unroll
            for (int p = 0; p < 2; p++) {
                float4 o = make_float4(v[rr][4 * p] * inv, v[rr][4 * p + 1] * inv,
                                       v[rr][4 * p + 2] * inv, v[rr][4 * p + 3] * inv);
                *(float4*)(orow + 128 * p) = o;
                *(float4*)(prow + 128 * p) = o;
            }
        }
        __syncthreads();                       // (2) Pd ready

        // prefetch Q for next pass (overlaps PV)
        if (pass < 15 && tid < 256) {
            int grow = (pass + 1) * 32 + qrow;
            int l = (grow >> 3) * 64 + w2 * 8 + (grow & 7);
            CP_ASYNC16(qr_base + (uint32_t)(qrow * 36 + qcq * 4) * 4,
                       Qg + (size_t)l * 256 + h * 32 + qcq * 4);
        }
        CP_COMMIT();

        // ================= PV phase (warp k-range: 16 k-pairs) ============
        ull pacc[4][8];
        #pragma unroll
        for (int j = 0; j < 4; j++)
            #pragma unroll
            for (int i = 0; i < 8; i++) pacc[j][i] = 0ull;
        {
            const float* Pk = Pd + rs * 516 + 32 * warp;
            const float* Vk = Vt + (8 * cq) * 512 + 32 * warp;
            #pragma unroll 4
            for (int a = 0; a < 16; a++) {
                ull p0 = *(const ull*)(Pk + 0 * 4128 + 2 * a);   // 8*516
                ull p1 = *(const ull*)(Pk + 1 * 4128 + 2 * a);
                ull p2 = *(const ull*)(Pk + 2 * 4128 + 2 * a);
                ull p3 = *(const ull*)(Pk + 3 * 4128 + 2 * a);
                int voff = 2 * (a ^ vsw);
                #pragma unroll
                for (int i = 0; i < 8; i++) {
                    ull vv = *(const ull*)(Vk + i * 512 + voff);
                    FMA2(pacc[0][i], p0, vv);
                    FMA2(pacc[1][i], p1, vv);
                    FMA2(pacc[2][i], p2, vv);
                    FMA2(pacc[3][i], p3, vv);
                }
            }
        }
        __syncthreads();                       // (3) PV done, Pd dead

        // ---- per-warp partials into Red[16][32][36] (aliases Pd) ----
        {
            float* rw = Red + warp * 32 * 36;
            #pragma unroll
            for (int j = 0; j < 4; j++) {
                int row = rs + 8 * j;
                float4 a4, b4;
                float2 f;
                f = *(float2*)&pacc[j][0]; a4.x = f.x + f.y;
                f = *(float2*)&pacc[j][1]; a4.y = f.x + f.y;
                f = *(float2*)&pacc[j][2]; a4.z = f.x + f.y;
                f = *(float2*)&pacc[j][3]; a4.w = f.x + f.y;
                f = *(float2*)&pacc[j][4]; b4.x = f.x + f.y;
                f = *(float2*)&pacc[j][5]; b4.y = f.x + f.y;
                f = *(float2*)&pacc[j][6]; b4.z = f.x + f.y;
                f = *(float2*)&pacc[j][7]; b4.w = f.x + f.y;
                *(float4*)(rw + row * 36 + 8 * cq)     = a4;
                *(float4*)(rw + row * 36 + 8 * cq + 4) = b4;
            }
        }
        __syncthreads();                       // (4) Red ready

        // ---- reduce 16 partials + fused LePE + STG x (threads 0..255) ----
        // NEW MAPPING: warp = channel quad (fixed c per warp), lane = row.
        // V tap loads: fixed c -> ko(r) spreads banks -> no 8-way conflict.
        if (tid < 256) {
            int r  = tid & 31;                 // token row within pass (lane)
            int c0 = (tid >> 5) * 4;           // channel quad (warp)
            float4 o = make_float4(0.f, 0.f, 0.f, 0.f);
            #pragma unroll
            for (int w = 0; w < 16; w++) {
                float4 t4 = *(const float4*)(Red + (w * 32 + r) * 36 + c0);
                o.x += t4.x; o.y += t4.y; o.z += t4.z; o.w += t4.w;
            }
            int t  = pass * 32 + r;            // window token
            int hs = t >> 3, ws = t & 7;
            float ov[4] = {o.x + Bsh[c0], o.y + Bsh[c0 + 1],
                           o.z + Bsh[c0 + 2], o.w + Bsh[c0 + 3]};
            int swc = 4 * ((c0 >> 3) & 3);
            #pragma unroll
            for (int dy = -1; dy <= 1; dy++) {
                if ((unsigned)(hs + dy) >= 64u) continue;
                #pragma unroll
                for (int dx = -1; dx <= 1; dx++) {
                    if ((unsigned)(ws + dx) >= 8u) continue;
                    int kk = t + dy * 8 + dx;
                    int ko = 2 * ((kk >> 1) ^ swc) + (kk & 1);
                    int wi = (dy + 1) * 3 + (dx + 1);
                    #pragma unroll
                    for (int cc = 0; cc < 4; cc++)
                        ov[cc] += Vt[(c0 + cc) * 512 + ko] * Wsh[(c0 + cc) * 9 + wi];
                }
            }
            int l = hs * 64 + w2 * 8 + ws;
            *(float4*)(xout + ((size_t)b * 4096 + l) * 256 + h * 32 + c0) =
                make_float4(ov[0], ov[1], ov[2], ov[3]);
        }

        CP_WAIT0();                            // Qr(pass+1) landed
        __syncthreads();                       // (5) epilogue done; Qr visible
    }
}

// ---------------------------------------------------------------------------
extern "C" void kernel_launch(void* const* d_in, const int* in_sizes, int n_in,
                              void* d_out, int out_size) {
    const float* qkv = (const float*)d_in[0];
    const float* cw  = (const float*)d_in[1];
    const float* cb  = (const float*)d_in[2];
    float* xout = (float*)d_out;
    float* attn = xout + (size_t)4 * 4096 * 256;    // x first, then attn

    const int SMEM = SMEM_FLOATS * 4;               // 210944 B
    cudaFuncSetAttribute(fused_attn_kernel,
                         cudaFuncAttributeMaxDynamicSharedMemorySize, SMEM);

    fused_attn_kernel<<<256, 512, SMEM>>>(qkv, cw, cb, attn, xout);
}